// round 4
// baseline (speedup 1.0000x reference)
#include <cuda_runtime.h>
#include <math.h>
#include <stdint.h>

// ---------------------------------------------------------------------------
// Problem constants (B=8, N=5376, Cin=384, Ch=768, H=W=32, n=256)
// ---------------------------------------------------------------------------
#define BB      8
#define NTOK    5376
#define CIN     384
#define CH      768
#define MROWS   (BB * NTOK)          // 43008

// ---------------------------------------------------------------------------
// Scratch (device globals; no runtime allocation)
// ---------------------------------------------------------------------------
__device__ float g_x [(size_t)MROWS * CIN];    // tf32-rounded copy of x
__device__ float g_h1[(size_t)MROWS * CH];     // fc1 output
__device__ float g_hc[(size_t)MROWS * CH];     // dwconv out -> gelu'd (tf32-rounded)
__device__ float g_w1[CIN * CH];               // fc1_w tf32-rounded [K,N]
__device__ float g_w2[CH * CIN];               // fc2_w tf32-rounded [K,N]
__device__ float g_avg[24 * CH];
__device__ float g_max[24 * CH];
__device__ float g_scale[24 * CH];

// ---------------------------------------------------------------------------
// Helpers
// ---------------------------------------------------------------------------
__device__ __forceinline__ float tf32r(float x) {
    uint32_t y;
    asm("cvt.rna.tf32.f32 %0, %1;" : "=r"(y) : "f"(x));
    return __uint_as_float(y);
}
__device__ __forceinline__ uint32_t smem_u32(const void* p) {
    uint32_t a;
    asm("{ .reg .u64 t; cvta.to.shared.u64 t, %1; cvt.u32.u64 %0, t; }"
        : "=r"(a) : "l"(p));
    return a;
}
__device__ __forceinline__ void cp16(uint32_t d, const void* s) {
    asm volatile("cp.async.cg.shared.global [%0], [%1], 16;\n" :: "r"(d), "l"(s));
}
__device__ __forceinline__ void mma_tf32(float& d0, float& d1, float& d2, float& d3,
                                         uint32_t a0, uint32_t a1, uint32_t a2, uint32_t a3,
                                         uint32_t b0, uint32_t b1) {
    asm volatile(
        "mma.sync.aligned.m16n8k8.row.col.f32.tf32.tf32.f32 "
        "{%0,%1,%2,%3}, {%4,%5,%6,%7}, {%8,%9}, {%0,%1,%2,%3};\n"
        : "+f"(d0), "+f"(d1), "+f"(d2), "+f"(d3)
        : "r"(a0), "r"(a1), "r"(a2), "r"(a3), "r"(b0), "r"(b1));
}

// ---------------------------------------------------------------------------
// TF32 tensor-core GEMM: C[M,N] = A[M,K] @ W[K,N] + bias[N]
// A and W must be tf32-pre-rounded (no cvt in the hot loop).
// BM=BN=128, BK=16, 256 threads (8 warps), warp tile 32x64,
// mma.sync.m16n8k8, 4-stage cp.async pipeline, ONE __syncthreads per tile.
// ---------------------------------------------------------------------------
#define BM 128
#define BN 128
#define BK 16
#define AROW 20          // As padded row (floats) -> conflict-free frag loads
#define BROW 136         // Bs padded row (floats) -> conflict-free frag loads
#define STAGES 4
#define AS_STAGE (BM * AROW)          // 2560 floats
#define BS_STAGE (BK * BROW)          // 2176 floats
#define GEMM_SMEM ((STAGES * (AS_STAGE + BS_STAGE)) * 4)   // 75776 bytes

__global__ void __launch_bounds__(256, 2)
gemm_tf32(const float* __restrict__ A, const float* __restrict__ W,
          const float* __restrict__ bias, float* __restrict__ C,
          int N, int K)
{
    extern __shared__ float sm[];
    float* AsBase = sm;
    float* BsBase = sm + STAGES * AS_STAGE;

    const int tid  = threadIdx.x;
    const int brow = blockIdx.y * BM;
    const int bcol = blockIdx.x * BN;

    const int lane = tid & 31;
    const int wid  = tid >> 5;
    const int g    = lane >> 2;    // 0..7
    const int tig  = lane & 3;     // 0..3
    const int wm   = wid & 3;      // warp m (32 rows)
    const int wn   = wid >> 2;     // warp n (64 cols)

    const uint32_t asU = smem_u32(AsBase);
    const uint32_t bsU = smem_u32(BsBase);

    const int ar  = tid >> 2;        // A row (+64 second pass)
    const int ac4 = (tid & 3) * 4;   // A k-col
    const int br  = tid >> 5;        // B k-row (+8 second pass)
    const int bc4 = (tid & 31) * 4;  // B col

    float acc[2][8][4];
#pragma unroll
    for (int mt = 0; mt < 2; mt++)
#pragma unroll
        for (int nt = 0; nt < 8; nt++)
#pragma unroll
            for (int v = 0; v < 4; v++) acc[mt][nt][v] = 0.0f;

    const int KT = K / BK;

    auto load_stage = [&](int st, int kt) {
        const uint32_t aD = asU + (uint32_t)(st * AS_STAGE * 4);
        const uint32_t bD = bsU + (uint32_t)(st * BS_STAGE * 4);
        cp16(aD + (uint32_t)((ar * AROW + ac4) * 4),
             A + (size_t)(brow + ar) * K + kt * BK + ac4);
        cp16(aD + (uint32_t)(((ar + 64) * AROW + ac4) * 4),
             A + (size_t)(brow + ar + 64) * K + kt * BK + ac4);
        cp16(bD + (uint32_t)((br * BROW + bc4) * 4),
             W + (size_t)(kt * BK + br) * N + bcol + bc4);
        cp16(bD + (uint32_t)(((br + 8) * BROW + bc4) * 4),
             W + (size_t)(kt * BK + br + 8) * N + bcol + bc4);
    };

    // prologue: stages 0..2
#pragma unroll
    for (int s = 0; s < STAGES - 1; s++) {
        load_stage(s, s);
        asm volatile("cp.async.commit_group;" ::: "memory");
    }

    for (int kt = 0; kt < KT; kt++) {
        const int cur = kt & (STAGES - 1);
        asm volatile("cp.async.wait_group 2;" ::: "memory");
        __syncthreads();

        // issue next-stage loads first (overlap with compute)
        if (kt + STAGES - 1 < KT)
            load_stage((kt + STAGES - 1) & (STAGES - 1), kt + STAGES - 1);
        asm volatile("cp.async.commit_group;" ::: "memory");

        const uint32_t* Asu = (const uint32_t*)(AsBase + cur * AS_STAGE);
        const uint32_t* Bsu = (const uint32_t*)(BsBase + cur * BS_STAGE);

#pragma unroll
        for (int kc = 0; kc < BK; kc += 8) {
            uint32_t af[2][4], bf[8][2];
#pragma unroll
            for (int mt = 0; mt < 2; mt++) {
                const int r0 = wm * 32 + mt * 16 + g;
                af[mt][0] = Asu[(r0    ) * AROW + kc + tig    ];
                af[mt][1] = Asu[(r0 + 8) * AROW + kc + tig    ];
                af[mt][2] = Asu[(r0    ) * AROW + kc + tig + 4];
                af[mt][3] = Asu[(r0 + 8) * AROW + kc + tig + 4];
            }
#pragma unroll
            for (int nt = 0; nt < 8; nt++) {
                const int c0 = wn * 64 + nt * 8 + g;
                bf[nt][0] = Bsu[(kc + tig    ) * BROW + c0];
                bf[nt][1] = Bsu[(kc + tig + 4) * BROW + c0];
            }
#pragma unroll
            for (int mt = 0; mt < 2; mt++)
#pragma unroll
                for (int nt = 0; nt < 8; nt++)
                    mma_tf32(acc[mt][nt][0], acc[mt][nt][1], acc[mt][nt][2], acc[mt][nt][3],
                             af[mt][0], af[mt][1], af[mt][2], af[mt][3],
                             bf[nt][0], bf[nt][1]);
        }
    }

    // ---- epilogue: bias + float2 stores ----
#pragma unroll
    for (int nt = 0; nt < 8; nt++) {
        const int col = bcol + wn * 64 + nt * 8 + 2 * tig;
        const float b0 = bias[col];
        const float b1 = bias[col + 1];
#pragma unroll
        for (int mt = 0; mt < 2; mt++) {
            const int row0 = brow + wm * 32 + mt * 16 + g;
            float2 o0 = make_float2(acc[mt][nt][0] + b0, acc[mt][nt][1] + b1);
            float2 o1 = make_float2(acc[mt][nt][2] + b0, acc[mt][nt][3] + b1);
            *(float2*)(C + (size_t)row0 * N + col)       = o0;
            *(float2*)(C + (size_t)(row0 + 8) * N + col) = o1;
        }
    }
}

// ---------------------------------------------------------------------------
// Round x -> tf32 (copy into g_x), float4
// ---------------------------------------------------------------------------
__global__ void __launch_bounds__(256)
round_x_kernel(const float* __restrict__ x)
{
    const size_t i = (size_t)blockIdx.x * 256 + threadIdx.x;
    const size_t nvec = (size_t)MROWS * CIN / 4;
    if (i >= nvec) return;
    float4 v = *(const float4*)(x + i * 4);
    v.x = tf32r(v.x); v.y = tf32r(v.y); v.z = tf32r(v.z); v.w = tf32r(v.w);
    *(float4*)(g_x + i * 4) = v;
}

// ---------------------------------------------------------------------------
// Round weights -> tf32 (same layout)
// ---------------------------------------------------------------------------
__global__ void __launch_bounds__(256)
round_w_kernel(const float* __restrict__ in, float* __restrict__ out, int n4)
{
    const int i = blockIdx.x * 256 + threadIdx.x;
    if (i >= n4) return;
    float4 v = *(const float4*)(in + (size_t)i * 4);
    v.x = tf32r(v.x); v.y = tf32r(v.y); v.z = tf32r(v.z); v.w = tf32r(v.w);
    *(float4*)(out + (size_t)i * 4) = v;
}

// ---------------------------------------------------------------------------
// Depthwise 3x3 conv + per-(scale,b,c) sum & max
// ---------------------------------------------------------------------------
__global__ void __launch_bounds__(256)
dwconv_kernel(const float* __restrict__ dw_w, const float* __restrict__ dw_b)
{
    const int s  = blockIdx.z;
    const int b  = blockIdx.y;
    const int cc = blockIdx.x;

    const int offs[3] = {0, 4096, 5120};
    const int lws[3]  = {6, 5, 4};
    const int off = offs[s];
    const int lw  = lws[s];
    const int w   = 1 << lw;
    const int ntok = w * w;

    const int tid   = threadIdx.x;
    const int c     = cc * 32 + (tid & 31);
    const int tslot = tid >> 5;

    float wgt[9];
#pragma unroll
    for (int i = 0; i < 9; i++) wgt[i] = dw_w[c * 9 + i];
    const float bk = dw_b[c];

    const float* base  = g_h1 + ((size_t)(b * NTOK + off)) * CH + c;
    float*       obase = g_hc + ((size_t)(b * NTOK + off)) * CH + c;

    float lsum = 0.0f;
    float lmax = -INFINITY;

    for (int tok = tslot; tok < ntok; tok += 8) {
        const int y = tok >> lw;
        const int x = tok & (w - 1);
        float acc = bk;
#pragma unroll
        for (int ky = 0; ky < 3; ky++) {
            const int yy = y + ky - 1;
            if ((unsigned)yy < (unsigned)w) {
                const int rb = yy << lw;
#pragma unroll
                for (int kx = 0; kx < 3; kx++) {
                    const int xx = x + kx - 1;
                    if ((unsigned)xx < (unsigned)w)
                        acc += wgt[ky * 3 + kx] * base[(size_t)(rb + xx) * CH];
                }
            }
        }
        obase[(size_t)tok * CH] = acc;
        lsum += acc;
        lmax = fmaxf(lmax, acc);
    }

    __shared__ float ssum[256];
    __shared__ float smax[256];
    ssum[tid] = lsum;
    smax[tid] = lmax;
    __syncthreads();
    if (tslot == 0) {
        float ts = lsum, tm = lmax;
#pragma unroll
        for (int j = 1; j < 8; j++) {
            ts += ssum[j * 32 + tid];
            tm = fmaxf(tm, smax[j * 32 + tid]);
        }
        const int sb = s * 8 + b;
        g_avg[sb * CH + c] = ts / (float)ntok;
        g_max[sb * CH + c] = tm;
    }
}

// ---------------------------------------------------------------------------
// Gate softmax + SE channel gates
// ---------------------------------------------------------------------------
__global__ void __launch_bounds__(256)
gate_scale_kernel(const float* __restrict__ gate_w, const float* __restrict__ gate_b,
                  const float* __restrict__ ca_w,   const float* __restrict__ ra_w)
{
    const int sb  = blockIdx.x;
    const int tid = threadIdx.x;

    __shared__ float pool[CH + 2];
    __shared__ float red0[256];
    __shared__ float red1[256];
    __shared__ float gw0s, gw1s;

    float d0 = 0.0f, d1 = 0.0f;
    for (int c = tid; c < CH; c += 256) {
        const float a = g_avg[sb * CH + c];
        const float m = g_max[sb * CH + c];
        pool[c + 1] = a + m;
        d0 += a * gate_w[c * 2 + 0];
        d1 += a * gate_w[c * 2 + 1];
    }
    if (tid == 0) { pool[0] = 0.0f; pool[CH + 1] = 0.0f; }
    red0[tid] = d0;
    red1[tid] = d1;
    __syncthreads();
    for (int sft = 128; sft > 0; sft >>= 1) {
        if (tid < sft) {
            red0[tid] += red0[tid + sft];
            red1[tid] += red1[tid + sft];
        }
        __syncthreads();
    }
    if (tid == 0) {
        const float l0 = red0[0] + gate_b[0];
        const float l1 = red1[0] + gate_b[1];
        const float m  = fmaxf(l0, l1);
        const float e0 = expf(l0 - m), e1 = expf(l1 - m);
        const float inv = 1.0f / (e0 + e1);
        gw0s = e0 * inv;
        gw1s = e1 * inv;
    }
    __syncthreads();

    const float c0 = ca_w[0], c1 = ca_w[1], c2 = ca_w[2];
    const float r0 = ra_w[0], r1 = ra_w[1], r2 = ra_w[2];
    const float gw0 = gw0s, gw1 = gw1s;
    for (int c = tid; c < CH; c += 256) {
        const float pm = pool[c], pc = pool[c + 1], pp = pool[c + 2];
        const float cav = c0 * pm + c1 * pc + c2 * pp;
        const float rav = r0 * pm + r1 * pc + r2 * pp;
        const float cas = 1.0f / (1.0f + expf(-cav));
        const float ras = 1.0f - 1.0f / (1.0f + expf(-rav));
        g_scale[sb * CH + c] = gw0 * cas + gw1 * ras;
    }
}

// ---------------------------------------------------------------------------
// Elementwise: g_hc <- tf32round(gelu_exact(g_hc * scale))
// ---------------------------------------------------------------------------
__device__ __forceinline__ float gelu_exact(float v)
{
    return 0.5f * v * (1.0f + erff(v * 0.70710678118654752440f));
}

__global__ void __launch_bounds__(256)
gelu_scale_kernel()
{
    const size_t nvec = (size_t)MROWS * CH / 4;
    const size_t i = (size_t)blockIdx.x * blockDim.x + threadIdx.x;
    if (i >= nvec) return;
    const size_t e   = i * 4;
    const int    row = (int)(e / CH);
    const int    c   = (int)(e % CH);
    const int    b   = row / NTOK;
    const int    tok = row % NTOK;
    const int    s   = (tok < 4096) ? 0 : ((tok < 5120) ? 1 : 2);

    float4 v  = *(const float4*)(g_hc + e);
    float4 sc = *(const float4*)(g_scale + (s * 8 + b) * CH + c);
    v.x = tf32r(gelu_exact(v.x * sc.x));
    v.y = tf32r(gelu_exact(v.y * sc.y));
    v.z = tf32r(gelu_exact(v.z * sc.z));
    v.w = tf32r(gelu_exact(v.w * sc.w));
    *(float4*)(g_hc + e) = v;
}

// ---------------------------------------------------------------------------
// Entry point
// ---------------------------------------------------------------------------
extern "C" void kernel_launch(void* const* d_in, const int* in_sizes, int n_in,
                              void* d_out, int out_size)
{
    const float* x      = (const float*)d_in[0];
    const float* fc1_w  = (const float*)d_in[1];
    const float* fc1_b  = (const float*)d_in[2];
    const float* dw_w   = (const float*)d_in[3];
    const float* dw_b   = (const float*)d_in[4];
    const float* ca_w   = (const float*)d_in[5];
    const float* ra_w   = (const float*)d_in[6];
    const float* gate_w = (const float*)d_in[7];
    const float* gate_b = (const float*)d_in[8];
    const float* fc2_w  = (const float*)d_in[9];
    const float* fc2_b  = (const float*)d_in[10];
    float* out = (float*)d_out;

    float *xr, *h1, *hc, *w1, *w2;
    cudaGetSymbolAddress((void**)&xr, g_x);
    cudaGetSymbolAddress((void**)&h1, g_h1);
    cudaGetSymbolAddress((void**)&hc, g_hc);
    cudaGetSymbolAddress((void**)&w1, g_w1);
    cudaGetSymbolAddress((void**)&w2, g_w2);

    cudaFuncSetAttribute(gemm_tf32, cudaFuncAttributeMaxDynamicSharedMemorySize,
                         GEMM_SMEM);

    // tf32-round inputs & weights
    round_x_kernel<<<(MROWS * CIN / 4 + 255) / 256, 256>>>(x);
    round_w_kernel<<<(CIN * CH / 4 + 255) / 256, 256>>>(fc1_w, w1, CIN * CH / 4);
    round_w_kernel<<<(CIN * CH / 4 + 255) / 256, 256>>>(fc2_w, w2, CIN * CH / 4);

    // fc1: (43008 x 384) @ (384 x 768) -> g_h1
    gemm_tf32<<<dim3(CH / BN, MROWS / BM), 256, GEMM_SMEM>>>(xr, w1, fc1_b, h1, CH, CIN);

    // depthwise conv + pooled stats
    dwconv_kernel<<<dim3(CH / 32, BB, 3), 256>>>(dw_w, dw_b);

    // gate softmax + SE channel gates
    gate_scale_kernel<<<24, 256>>>(gate_w, gate_b, ca_w, ra_w);

    // scale + exact GELU (+ tf32 round, in place on g_hc)
    const int nvec = MROWS * CH / 4;
    gelu_scale_kernel<<<(nvec + 255) / 256, 256>>>();

    // fc2: (43008 x 768) @ (768 x 384) + bias -> out
    gemm_tf32<<<dim3(CIN / BN, MROWS / BM), 256, GEMM_SMEM>>>(hc, w2, fc2_b, out, CIN, CH);
}

// round 5
// speedup vs baseline: 1.2623x; 1.2623x over previous
#include <cuda_runtime.h>
#include <cuda_fp16.h>
#include <math.h>
#include <stdint.h>

// ---------------------------------------------------------------------------
// Problem constants (B=8, N=5376, Cin=384, Ch=768, H=W=32, n=256)
// ---------------------------------------------------------------------------
#define BB      8
#define NTOK    5376
#define CIN     384
#define CH      768
#define MROWS   (BB * NTOK)          // 43008

// ---------------------------------------------------------------------------
// Scratch (device globals; no runtime allocation)
// ---------------------------------------------------------------------------
__device__ uint32_t g_xh [(size_t)MROWS * CIN / 2];   // x as half2-pairs along K
__device__ float    g_h1 [(size_t)MROWS * CH];        // fc1 output (fp32)
__device__ float    g_hc [(size_t)MROWS * CH];        // dwconv output (fp32)
__device__ uint32_t g_hch[(size_t)MROWS * CH / 2];    // gelu output as half2 pairs
__device__ uint32_t g_w1p[(CIN / 2) * CH];            // fc1_w pair-interleaved
__device__ uint32_t g_w2p[(CH / 2) * CIN];            // fc2_w pair-interleaved
__device__ float    g_avg[24 * CH];
__device__ float    g_max[24 * CH];
__device__ float    g_scale[24 * CH];

// ---------------------------------------------------------------------------
// Helpers
// ---------------------------------------------------------------------------
__device__ __forceinline__ uint32_t smem_u32(const void* p) {
    uint32_t a;
    asm("{ .reg .u64 t; cvta.to.shared.u64 t, %1; cvt.u32.u64 %0, t; }"
        : "=r"(a) : "l"(p));
    return a;
}
__device__ __forceinline__ void cp16(uint32_t d, const void* s) {
    asm volatile("cp.async.cg.shared.global [%0], [%1], 16;\n" :: "r"(d), "l"(s));
}
__device__ __forceinline__ uint32_t pack_h2(float a, float b) {
    __half2 h = __floats2half2_rn(a, b);
    return *(uint32_t*)&h;
}
__device__ __forceinline__ void mma_f16(float& d0, float& d1, float& d2, float& d3,
                                        uint32_t a0, uint32_t a1, uint32_t a2, uint32_t a3,
                                        uint32_t b0, uint32_t b1) {
    asm volatile(
        "mma.sync.aligned.m16n8k16.row.col.f32.f16.f16.f32 "
        "{%0,%1,%2,%3}, {%4,%5,%6,%7}, {%8,%9}, {%0,%1,%2,%3};\n"
        : "+f"(d0), "+f"(d1), "+f"(d2), "+f"(d3)
        : "r"(a0), "r"(a1), "r"(a2), "r"(a3), "r"(b0), "r"(b1));
}

// ---------------------------------------------------------------------------
// FP16 tensor-core GEMM: C[M,N] = A[M,K] @ W[K,N] + bias[N]   (fp32 accum)
// A: [M][K2] u32 half2 pairs along K.  Wp: [K2][N] u32, pair-interleaved.
// BM=BN=128, BK2=16 u32 (K=32) per stage, 256 threads, warp tile 32x64,
// mma.m16n8k16, 4-stage cp.async pipeline, one __syncthreads per stage.
// ---------------------------------------------------------------------------
#define BM 128
#define BN 128
#define BK2 16
#define AROW 20
#define BROW 136
#define STAGES 4
#define AS_STAGE (BM * AROW)          // 2560 u32
#define BS_STAGE (BK2 * BROW)         // 2176 u32
#define GEMM_SMEM ((STAGES * (AS_STAGE + BS_STAGE)) * 4)   // 75776 bytes

__global__ void __launch_bounds__(256, 2)
gemm_f16(const uint32_t* __restrict__ A, const uint32_t* __restrict__ Wp,
         const float* __restrict__ bias, float* __restrict__ C,
         int N, int K2)
{
    extern __shared__ uint32_t sm[];
    uint32_t* AsBase = sm;
    uint32_t* BsBase = sm + STAGES * AS_STAGE;

    const int tid  = threadIdx.x;
    const int brow = blockIdx.y * BM;
    const int bcol = blockIdx.x * BN;

    const int lane = tid & 31;
    const int wid  = tid >> 5;
    const int g    = lane >> 2;
    const int tig  = lane & 3;
    const int wm   = wid & 3;      // warp m (32 rows)
    const int wn   = wid >> 2;     // warp n (64 cols)

    const uint32_t asU = smem_u32(AsBase);
    const uint32_t bsU = smem_u32(BsBase);

    const int ar  = tid >> 2;        // A row (+64 second pass)
    const int ac4 = (tid & 3) * 4;   // A k2-col (u32)
    const int br  = tid >> 5;        // B k2-row (+8 second pass)
    const int bc4 = (tid & 31) * 4;  // B col (u32)

    float acc[2][8][4];
#pragma unroll
    for (int mt = 0; mt < 2; mt++)
#pragma unroll
        for (int nt = 0; nt < 8; nt++)
#pragma unroll
            for (int v = 0; v < 4; v++) acc[mt][nt][v] = 0.0f;

    const int KT = K2 / BK2;

    auto load_stage = [&](int st, int kt) {
        const uint32_t aD = asU + (uint32_t)(st * AS_STAGE * 4);
        const uint32_t bD = bsU + (uint32_t)(st * BS_STAGE * 4);
        cp16(aD + (uint32_t)((ar * AROW + ac4) * 4),
             A + (size_t)(brow + ar) * K2 + kt * BK2 + ac4);
        cp16(aD + (uint32_t)(((ar + 64) * AROW + ac4) * 4),
             A + (size_t)(brow + ar + 64) * K2 + kt * BK2 + ac4);
        cp16(bD + (uint32_t)((br * BROW + bc4) * 4),
             Wp + (size_t)(kt * BK2 + br) * N + bcol + bc4);
        cp16(bD + (uint32_t)(((br + 8) * BROW + bc4) * 4),
             Wp + (size_t)(kt * BK2 + br + 8) * N + bcol + bc4);
    };

#pragma unroll
    for (int s = 0; s < STAGES - 1; s++) {
        load_stage(s, s);
        asm volatile("cp.async.commit_group;" ::: "memory");
    }

    for (int kt = 0; kt < KT; kt++) {
        const int cur = kt & (STAGES - 1);
        asm volatile("cp.async.wait_group 2;" ::: "memory");
        __syncthreads();

        if (kt + STAGES - 1 < KT)
            load_stage((kt + STAGES - 1) & (STAGES - 1), kt + STAGES - 1);
        asm volatile("cp.async.commit_group;" ::: "memory");

        const uint32_t* Asu = AsBase + cur * AS_STAGE;
        const uint32_t* Bsu = BsBase + cur * BS_STAGE;

#pragma unroll
        for (int kc = 0; kc < BK2; kc += 8) {
            uint32_t af[2][4], bf[8][2];
#pragma unroll
            for (int mt = 0; mt < 2; mt++) {
                const int r0 = wm * 32 + mt * 16 + g;
                af[mt][0] = Asu[(r0    ) * AROW + kc + tig    ];
                af[mt][1] = Asu[(r0 + 8) * AROW + kc + tig    ];
                af[mt][2] = Asu[(r0    ) * AROW + kc + tig + 4];
                af[mt][3] = Asu[(r0 + 8) * AROW + kc + tig + 4];
            }
#pragma unroll
            for (int nt = 0; nt < 8; nt++) {
                const int c0 = wn * 64 + nt * 8 + g;
                bf[nt][0] = Bsu[(kc + tig    ) * BROW + c0];
                bf[nt][1] = Bsu[(kc + tig + 4) * BROW + c0];
            }
#pragma unroll
            for (int mt = 0; mt < 2; mt++)
#pragma unroll
                for (int nt = 0; nt < 8; nt++)
                    mma_f16(acc[mt][nt][0], acc[mt][nt][1], acc[mt][nt][2], acc[mt][nt][3],
                            af[mt][0], af[mt][1], af[mt][2], af[mt][3],
                            bf[nt][0], bf[nt][1]);
        }
    }

    // ---- epilogue: bias + float2 stores ----
#pragma unroll
    for (int nt = 0; nt < 8; nt++) {
        const int col = bcol + wn * 64 + nt * 8 + 2 * tig;
        const float b0 = bias[col];
        const float b1 = bias[col + 1];
#pragma unroll
        for (int mt = 0; mt < 2; mt++) {
            const int row0 = brow + wm * 32 + mt * 16 + g;
            float2 o0 = make_float2(acc[mt][nt][0] + b0, acc[mt][nt][1] + b1);
            float2 o1 = make_float2(acc[mt][nt][2] + b0, acc[mt][nt][3] + b1);
            *(float2*)(C + (size_t)row0 * N + col)       = o0;
            *(float2*)(C + (size_t)(row0 + 8) * N + col) = o1;
        }
    }
}

// ---------------------------------------------------------------------------
// Convert x -> half pairs (g_xh)
// ---------------------------------------------------------------------------
__global__ void __launch_bounds__(256)
convert_x_kernel(const float* __restrict__ x)
{
    const size_t i = (size_t)blockIdx.x * 256 + threadIdx.x;
    const size_t nvec = (size_t)MROWS * CIN / 4;
    if (i >= nvec) return;
    float4 v = *(const float4*)(x + i * 4);
    uint2 o;
    o.x = pack_h2(v.x, v.y);
    o.y = pack_h2(v.z, v.w);
    *(uint2*)(g_xh + i * 2) = o;
}

// ---------------------------------------------------------------------------
// Pack weights: out[k2*N + n] = half2(in[(2k2)*N+n], in[(2k2+1)*N+n])
// ---------------------------------------------------------------------------
__global__ void __launch_bounds__(256)
pack_w_kernel(const float* __restrict__ in, uint32_t* __restrict__ out,
              int K2, int N)
{
    const int idx = blockIdx.x * 256 + threadIdx.x;
    if (idx >= K2 * N) return;
    const int k2 = idx / N;
    const int n  = idx % N;
    const float f0 = in[(size_t)(2 * k2)     * N + n];
    const float f1 = in[(size_t)(2 * k2 + 1) * N + n];
    out[idx] = pack_h2(f0, f1);
}

// ---------------------------------------------------------------------------
// Depthwise 3x3 conv + per-(scale,b,c) sum & max (fp32, unchanged)
// ---------------------------------------------------------------------------
__global__ void __launch_bounds__(256)
dwconv_kernel(const float* __restrict__ dw_w, const float* __restrict__ dw_b)
{
    const int s  = blockIdx.z;
    const int b  = blockIdx.y;
    const int cc = blockIdx.x;

    const int offs[3] = {0, 4096, 5120};
    const int lws[3]  = {6, 5, 4};
    const int off = offs[s];
    const int lw  = lws[s];
    const int w   = 1 << lw;
    const int ntok = w * w;

    const int tid   = threadIdx.x;
    const int c     = cc * 32 + (tid & 31);
    const int tslot = tid >> 5;

    float wgt[9];
#pragma unroll
    for (int i = 0; i < 9; i++) wgt[i] = dw_w[c * 9 + i];
    const float bk = dw_b[c];

    const float* base  = g_h1 + ((size_t)(b * NTOK + off)) * CH + c;
    float*       obase = g_hc + ((size_t)(b * NTOK + off)) * CH + c;

    float lsum = 0.0f;
    float lmax = -INFINITY;

    for (int tok = tslot; tok < ntok; tok += 8) {
        const int y = tok >> lw;
        const int x = tok & (w - 1);
        float acc = bk;
#pragma unroll
        for (int ky = 0; ky < 3; ky++) {
            const int yy = y + ky - 1;
            if ((unsigned)yy < (unsigned)w) {
                const int rb = yy << lw;
#pragma unroll
                for (int kx = 0; kx < 3; kx++) {
                    const int xx = x + kx - 1;
                    if ((unsigned)xx < (unsigned)w)
                        acc += wgt[ky * 3 + kx] * base[(size_t)(rb + xx) * CH];
                }
            }
        }
        obase[(size_t)tok * CH] = acc;
        lsum += acc;
        lmax = fmaxf(lmax, acc);
    }

    __shared__ float ssum[256];
    __shared__ float smax[256];
    ssum[tid] = lsum;
    smax[tid] = lmax;
    __syncthreads();
    if (tslot == 0) {
        float ts = lsum, tm = lmax;
#pragma unroll
        for (int j = 1; j < 8; j++) {
            ts += ssum[j * 32 + tid];
            tm = fmaxf(tm, smax[j * 32 + tid]);
        }
        const int sb = s * 8 + b;
        g_avg[sb * CH + c] = ts / (float)ntok;
        g_max[sb * CH + c] = tm;
    }
}

// ---------------------------------------------------------------------------
// Gate softmax + SE channel gates (unchanged)
// ---------------------------------------------------------------------------
__global__ void __launch_bounds__(256)
gate_scale_kernel(const float* __restrict__ gate_w, const float* __restrict__ gate_b,
                  const float* __restrict__ ca_w,   const float* __restrict__ ra_w)
{
    const int sb  = blockIdx.x;
    const int tid = threadIdx.x;

    __shared__ float pool[CH + 2];
    __shared__ float red0[256];
    __shared__ float red1[256];
    __shared__ float gw0s, gw1s;

    float d0 = 0.0f, d1 = 0.0f;
    for (int c = tid; c < CH; c += 256) {
        const float a = g_avg[sb * CH + c];
        const float m = g_max[sb * CH + c];
        pool[c + 1] = a + m;
        d0 += a * gate_w[c * 2 + 0];
        d1 += a * gate_w[c * 2 + 1];
    }
    if (tid == 0) { pool[0] = 0.0f; pool[CH + 1] = 0.0f; }
    red0[tid] = d0;
    red1[tid] = d1;
    __syncthreads();
    for (int sft = 128; sft > 0; sft >>= 1) {
        if (tid < sft) {
            red0[tid] += red0[tid + sft];
            red1[tid] += red1[tid + sft];
        }
        __syncthreads();
    }
    if (tid == 0) {
        const float l0 = red0[0] + gate_b[0];
        const float l1 = red1[0] + gate_b[1];
        const float m  = fmaxf(l0, l1);
        const float e0 = expf(l0 - m), e1 = expf(l1 - m);
        const float inv = 1.0f / (e0 + e1);
        gw0s = e0 * inv;
        gw1s = e1 * inv;
    }
    __syncthreads();

    const float c0 = ca_w[0], c1 = ca_w[1], c2 = ca_w[2];
    const float r0 = ra_w[0], r1 = ra_w[1], r2 = ra_w[2];
    const float gw0 = gw0s, gw1 = gw1s;
    for (int c = tid; c < CH; c += 256) {
        const float pm = pool[c], pc = pool[c + 1], pp = pool[c + 2];
        const float cav = c0 * pm + c1 * pc + c2 * pp;
        const float rav = r0 * pm + r1 * pc + r2 * pp;
        const float cas = 1.0f / (1.0f + expf(-cav));
        const float ras = 1.0f - 1.0f / (1.0f + expf(-rav));
        g_scale[sb * CH + c] = gw0 * cas + gw1 * ras;
    }
}

// ---------------------------------------------------------------------------
// Elementwise: g_hch <- half(gelu_exact(g_hc * scale))
// ---------------------------------------------------------------------------
__device__ __forceinline__ float gelu_exact(float v)
{
    return 0.5f * v * (1.0f + erff(v * 0.70710678118654752440f));
}

__global__ void __launch_bounds__(256)
gelu_scale_kernel()
{
    const size_t nvec = (size_t)MROWS * CH / 4;
    const size_t i = (size_t)blockIdx.x * blockDim.x + threadIdx.x;
    if (i >= nvec) return;
    const size_t e   = i * 4;
    const int    row = (int)(e / CH);
    const int    c   = (int)(e % CH);
    const int    b   = row / NTOK;
    const int    tok = row % NTOK;
    const int    s   = (tok < 4096) ? 0 : ((tok < 5120) ? 1 : 2);

    float4 v  = *(const float4*)(g_hc + e);
    float4 sc = *(const float4*)(g_scale + (s * 8 + b) * CH + c);
    uint2 o;
    o.x = pack_h2(gelu_exact(v.x * sc.x), gelu_exact(v.y * sc.y));
    o.y = pack_h2(gelu_exact(v.z * sc.z), gelu_exact(v.w * sc.w));
    *(uint2*)(g_hch + i * 2) = o;
}

// ---------------------------------------------------------------------------
// Entry point
// ---------------------------------------------------------------------------
extern "C" void kernel_launch(void* const* d_in, const int* in_sizes, int n_in,
                              void* d_out, int out_size)
{
    const float* x      = (const float*)d_in[0];
    const float* fc1_w  = (const float*)d_in[1];
    const float* fc1_b  = (const float*)d_in[2];
    const float* dw_w   = (const float*)d_in[3];
    const float* dw_b   = (const float*)d_in[4];
    const float* ca_w   = (const float*)d_in[5];
    const float* ra_w   = (const float*)d_in[6];
    const float* gate_w = (const float*)d_in[7];
    const float* gate_b = (const float*)d_in[8];
    const float* fc2_w  = (const float*)d_in[9];
    const float* fc2_b  = (const float*)d_in[10];
    float* out = (float*)d_out;

    uint32_t *xh, *hch, *w1p, *w2p;
    float *h1;
    cudaGetSymbolAddress((void**)&xh,  g_xh);
    cudaGetSymbolAddress((void**)&h1,  g_h1);
    cudaGetSymbolAddress((void**)&hch, g_hch);
    cudaGetSymbolAddress((void**)&w1p, g_w1p);
    cudaGetSymbolAddress((void**)&w2p, g_w2p);

    cudaFuncSetAttribute(gemm_f16, cudaFuncAttributeMaxDynamicSharedMemorySize,
                         GEMM_SMEM);

    // convert inputs & weights to fp16 (pair-interleaved weights)
    convert_x_kernel<<<(MROWS * CIN / 4 + 255) / 256, 256>>>(x);
    pack_w_kernel<<<((CIN / 2) * CH + 255) / 256, 256>>>(fc1_w, w1p, CIN / 2, CH);
    pack_w_kernel<<<((CH / 2) * CIN + 255) / 256, 256>>>(fc2_w, w2p, CH / 2, CIN);

    // fc1: (43008 x 384) @ (384 x 768) -> g_h1 (fp32)
    gemm_f16<<<dim3(CH / BN, MROWS / BM), 256, GEMM_SMEM>>>(xh, w1p, fc1_b, h1, CH, CIN / 2);

    // depthwise conv + pooled stats
    dwconv_kernel<<<dim3(CH / 32, BB, 3), 256>>>(dw_w, dw_b);

    // gate softmax + SE channel gates
    gate_scale_kernel<<<24, 256>>>(gate_w, gate_b, ca_w, ra_w);

    // scale + exact GELU -> half pairs (g_hch)
    const int nvec = MROWS * CH / 4;
    gelu_scale_kernel<<<(nvec + 255) / 256, 256>>>();

    // fc2: (43008 x 768) @ (768 x 384) + bias -> out (fp32)
    gemm_f16<<<dim3(CIN / BN, MROWS / BM), 256, GEMM_SMEM>>>(hch, w2p, fc2_b, out, CIN, CH / 2);
}

// round 6
// speedup vs baseline: 1.3352x; 1.0577x over previous
#include <cuda_runtime.h>
#include <cuda_fp16.h>
#include <math.h>
#include <stdint.h>

// ---------------------------------------------------------------------------
// Problem constants (B=8, N=5376, Cin=384, Ch=768, H=W=32, n=256)
// ---------------------------------------------------------------------------
#define BB      8
#define NTOK    5376
#define CIN     384
#define CH      768
#define MROWS   (BB * NTOK)          // 43008

// ---------------------------------------------------------------------------
// Scratch (device globals; no runtime allocation)
// ---------------------------------------------------------------------------
__device__ uint32_t g_xh [(size_t)MROWS * CIN / 2];   // x as plain half (pairs along K)
__device__ __half   g_h1h[(size_t)MROWS * CH];        // fc1 output, half
__device__ __half   g_hch[(size_t)MROWS * CH];        // dwconv out -> gelu'd in place
__device__ uint32_t g_w1p[(CIN / 2) * CH];            // fc1_w pair-interleaved
__device__ uint32_t g_w2p[(CH / 2) * CIN];            // fc2_w pair-interleaved
__device__ float    g_avg[24 * CH];
__device__ float    g_max[24 * CH];
__device__ float    g_scale[24 * CH];

// ---------------------------------------------------------------------------
// Helpers
// ---------------------------------------------------------------------------
__device__ __forceinline__ uint32_t smem_u32(const void* p) {
    uint32_t a;
    asm("{ .reg .u64 t; cvta.to.shared.u64 t, %1; cvt.u32.u64 %0, t; }"
        : "=r"(a) : "l"(p));
    return a;
}
__device__ __forceinline__ void cp16(uint32_t d, const void* s) {
    asm volatile("cp.async.cg.shared.global [%0], [%1], 16;\n" :: "r"(d), "l"(s));
}
__device__ __forceinline__ uint32_t pack_h2(float a, float b) {
    __half2 h = __floats2half2_rn(a, b);
    return *(uint32_t*)&h;
}
__device__ __forceinline__ void mma_f16(float& d0, float& d1, float& d2, float& d3,
                                        uint32_t a0, uint32_t a1, uint32_t a2, uint32_t a3,
                                        uint32_t b0, uint32_t b1) {
    asm volatile(
        "mma.sync.aligned.m16n8k16.row.col.f32.f16.f16.f32 "
        "{%0,%1,%2,%3}, {%4,%5,%6,%7}, {%8,%9}, {%0,%1,%2,%3};\n"
        : "+f"(d0), "+f"(d1), "+f"(d2), "+f"(d3)
        : "r"(a0), "r"(a1), "r"(a2), "r"(a3), "r"(b0), "r"(b1));
}
__device__ __forceinline__ void ldsm_x4(uint32_t& r0, uint32_t& r1,
                                        uint32_t& r2, uint32_t& r3, uint32_t addr) {
    asm volatile("ldmatrix.sync.aligned.m8n8.x4.shared.b16 {%0,%1,%2,%3}, [%4];"
                 : "=r"(r0), "=r"(r1), "=r"(r2), "=r"(r3) : "r"(addr));
}

// ---------------------------------------------------------------------------
// FP16 GEMM: C[M,N] = A[M,K] @ W[K,N] + bias[N]   (fp32 accum)
// A: [M][K2] u32 half-pairs along K.  Wp: [K2][N] u32 pair-interleaved.
// 128 threads (4 warps, 2x2 warp grid), warp tile 64x64, BK2=16 (K=32),
// ldmatrix.x4 A-fragments, 4-stage cp.async, one barrier per stage.
// ---------------------------------------------------------------------------
#define BM 128
#define BN 128
#define BK2 16
#define AROW 20
#define BROW 136
#define STAGES 4
#define AS_STAGE (BM * AROW)          // 2560 u32
#define BS_STAGE (BK2 * BROW)         // 2176 u32
#define GEMM_SMEM ((STAGES * (AS_STAGE + BS_STAGE)) * 4)   // 75776 bytes

template<bool HALF_OUT>
__global__ void __launch_bounds__(128, 2)
gemm_f16(const uint32_t* __restrict__ A, const uint32_t* __restrict__ Wp,
         const float* __restrict__ bias, void* __restrict__ Cout,
         int N, int K2)
{
    extern __shared__ uint32_t sm[];
    uint32_t* AsBase = sm;
    uint32_t* BsBase = sm + STAGES * AS_STAGE;

    const int tid  = threadIdx.x;
    const int brow = blockIdx.y * BM;
    const int bcol = blockIdx.x * BN;

    const int lane = tid & 31;
    const int wid  = tid >> 5;
    const int g    = lane >> 2;
    const int tig  = lane & 3;
    const int wm   = wid & 1;      // warp m (64 rows)
    const int wn   = wid >> 1;     // warp n (64 cols)

    const uint32_t asU = smem_u32(AsBase);
    const uint32_t bsU = smem_u32(BsBase);

    float acc[4][8][4];
#pragma unroll
    for (int mt = 0; mt < 4; mt++)
#pragma unroll
        for (int nt = 0; nt < 8; nt++)
#pragma unroll
            for (int v = 0; v < 4; v++) acc[mt][nt][v] = 0.0f;

    const int KT = K2 / BK2;

    auto load_stage = [&](int st, int kt) {
        const uint32_t aD = asU + (uint32_t)(st * AS_STAGE * 4);
        const uint32_t bD = bsU + (uint32_t)(st * BS_STAGE * 4);
#pragma unroll
        for (int u = 0; u < 4; u++) {
            const int li = u * 128 + tid;
            const int r = li >> 2;
            const int c = (li & 3) * 4;
            cp16(aD + (uint32_t)((r * AROW + c) * 4),
                 A + (size_t)(brow + r) * K2 + kt * BK2 + c);
        }
#pragma unroll
        for (int u = 0; u < 4; u++) {
            const int li = u * 128 + tid;
            const int r = li >> 5;
            const int c = (li & 31) * 4;
            cp16(bD + (uint32_t)((r * BROW + c) * 4),
                 Wp + (size_t)(kt * BK2 + r) * N + bcol + c);
        }
    };

#pragma unroll
    for (int s = 0; s < STAGES - 1; s++) {
        load_stage(s, s);
        asm volatile("cp.async.commit_group;" ::: "memory");
    }

    // ldmatrix lane addressing: row = (lane&15), k-offset u32 = (lane>>4)*4
    const int lm_row = lane & 15;
    const int lm_koff = (lane >> 4) << 2;

    for (int kt = 0; kt < KT; kt++) {
        const int cur = kt & (STAGES - 1);
        asm volatile("cp.async.wait_group 2;" ::: "memory");
        __syncthreads();

        if (kt + STAGES - 1 < KT)
            load_stage((kt + STAGES - 1) & (STAGES - 1), kt + STAGES - 1);
        asm volatile("cp.async.commit_group;" ::: "memory");

        const uint32_t  aStage = asU + (uint32_t)(cur * AS_STAGE * 4);
        const uint32_t* Bsu    = BsBase + cur * BS_STAGE;

#pragma unroll
        for (int kc = 0; kc < BK2; kc += 8) {
            uint32_t af[4][4], bf[8][2];
#pragma unroll
            for (int mt = 0; mt < 4; mt++) {
                const int r = wm * 64 + mt * 16 + lm_row;
                const uint32_t addr = aStage + (uint32_t)((r * AROW + kc + lm_koff) * 4);
                ldsm_x4(af[mt][0], af[mt][1], af[mt][2], af[mt][3], addr);
            }
#pragma unroll
            for (int nt = 0; nt < 8; nt++) {
                const int c0 = wn * 64 + nt * 8 + g;
                bf[nt][0] = Bsu[(kc + tig    ) * BROW + c0];
                bf[nt][1] = Bsu[(kc + tig + 4) * BROW + c0];
            }
#pragma unroll
            for (int mt = 0; mt < 4; mt++)
#pragma unroll
                for (int nt = 0; nt < 8; nt++)
                    mma_f16(acc[mt][nt][0], acc[mt][nt][1], acc[mt][nt][2], acc[mt][nt][3],
                            af[mt][0], af[mt][1], af[mt][2], af[mt][3],
                            bf[nt][0], bf[nt][1]);
        }
    }

    // ---- epilogue ----
#pragma unroll
    for (int nt = 0; nt < 8; nt++) {
        const int col = bcol + wn * 64 + nt * 8 + 2 * tig;
        const float b0 = bias[col];
        const float b1 = bias[col + 1];
#pragma unroll
        for (int mt = 0; mt < 4; mt++) {
            const int row0 = brow + wm * 64 + mt * 16 + g;
            if (HALF_OUT) {
                uint32_t* Ch = (uint32_t*)Cout;
                Ch[(size_t)row0 * (N / 2) + col / 2] =
                    pack_h2(acc[mt][nt][0] + b0, acc[mt][nt][1] + b1);
                Ch[(size_t)(row0 + 8) * (N / 2) + col / 2] =
                    pack_h2(acc[mt][nt][2] + b0, acc[mt][nt][3] + b1);
            } else {
                float* Cf = (float*)Cout;
                *(float2*)(Cf + (size_t)row0 * N + col) =
                    make_float2(acc[mt][nt][0] + b0, acc[mt][nt][1] + b1);
                *(float2*)(Cf + (size_t)(row0 + 8) * N + col) =
                    make_float2(acc[mt][nt][2] + b0, acc[mt][nt][3] + b1);
            }
        }
    }
}

// ---------------------------------------------------------------------------
// Convert x -> plain half (g_xh)
// ---------------------------------------------------------------------------
__global__ void __launch_bounds__(256)
convert_x_kernel(const float* __restrict__ x)
{
    const size_t i = (size_t)blockIdx.x * 256 + threadIdx.x;
    const size_t nvec = (size_t)MROWS * CIN / 4;
    if (i >= nvec) return;
    float4 v = *(const float4*)(x + i * 4);
    uint2 o;
    o.x = pack_h2(v.x, v.y);
    o.y = pack_h2(v.z, v.w);
    *(uint2*)(g_xh + i * 2) = o;
}

// ---------------------------------------------------------------------------
// Pack weights: out[k2*N + n] = half2(in[2k2][n], in[2k2+1][n])
// ---------------------------------------------------------------------------
__global__ void __launch_bounds__(256)
pack_w_kernel(const float* __restrict__ in, uint32_t* __restrict__ out,
              int K2, int N)
{
    const int idx = blockIdx.x * 256 + threadIdx.x;
    if (idx >= K2 * N) return;
    const int k2 = idx / N;
    const int n  = idx % N;
    out[idx] = pack_h2(in[(size_t)(2 * k2) * N + n],
                       in[(size_t)(2 * k2 + 1) * N + n]);
}

// ---------------------------------------------------------------------------
// Depthwise 3x3 conv (half in/out, fp32 accum) + per-(scale,b,c) sum & max
// ---------------------------------------------------------------------------
__global__ void __launch_bounds__(256)
dwconv_kernel(const float* __restrict__ dw_w, const float* __restrict__ dw_b)
{
    const int s  = blockIdx.z;
    const int b  = blockIdx.y;
    const int cc = blockIdx.x;

    const int offs[3] = {0, 4096, 5120};
    const int lws[3]  = {6, 5, 4};
    const int off = offs[s];
    const int lw  = lws[s];
    const int w   = 1 << lw;
    const int ntok = w * w;

    const int tid   = threadIdx.x;
    const int c     = cc * 32 + (tid & 31);
    const int tslot = tid >> 5;

    float wgt[9];
#pragma unroll
    for (int i = 0; i < 9; i++) wgt[i] = dw_w[c * 9 + i];
    const float bk = dw_b[c];

    const __half* base  = g_h1h + ((size_t)(b * NTOK + off)) * CH + c;
    __half*       obase = g_hch + ((size_t)(b * NTOK + off)) * CH + c;

    float lsum = 0.0f;
    float lmax = -INFINITY;

    for (int tok = tslot; tok < ntok; tok += 8) {
        const int y = tok >> lw;
        const int x = tok & (w - 1);
        float acc = bk;
#pragma unroll
        for (int ky = 0; ky < 3; ky++) {
            const int yy = y + ky - 1;
            if ((unsigned)yy < (unsigned)w) {
                const int rb = yy << lw;
#pragma unroll
                for (int kx = 0; kx < 3; kx++) {
                    const int xx = x + kx - 1;
                    if ((unsigned)xx < (unsigned)w)
                        acc += wgt[ky * 3 + kx] *
                               __half2float(base[(size_t)(rb + xx) * CH]);
                }
            }
        }
        obase[(size_t)tok * CH] = __float2half_rn(acc);
        lsum += acc;
        lmax = fmaxf(lmax, acc);
    }

    __shared__ float ssum[256];
    __shared__ float smax[256];
    ssum[tid] = lsum;
    smax[tid] = lmax;
    __syncthreads();
    if (tslot == 0) {
        float ts = lsum, tm = lmax;
#pragma unroll
        for (int j = 1; j < 8; j++) {
            ts += ssum[j * 32 + tid];
            tm = fmaxf(tm, smax[j * 32 + tid]);
        }
        const int sb = s * 8 + b;
        g_avg[sb * CH + c] = ts / (float)ntok;
        g_max[sb * CH + c] = tm;
    }
}

// ---------------------------------------------------------------------------
// Gate softmax + SE channel gates (unchanged)
// ---------------------------------------------------------------------------
__global__ void __launch_bounds__(256)
gate_scale_kernel(const float* __restrict__ gate_w, const float* __restrict__ gate_b,
                  const float* __restrict__ ca_w,   const float* __restrict__ ra_w)
{
    const int sb  = blockIdx.x;
    const int tid = threadIdx.x;

    __shared__ float pool[CH + 2];
    __shared__ float red0[256];
    __shared__ float red1[256];
    __shared__ float gw0s, gw1s;

    float d0 = 0.0f, d1 = 0.0f;
    for (int c = tid; c < CH; c += 256) {
        const float a = g_avg[sb * CH + c];
        const float m = g_max[sb * CH + c];
        pool[c + 1] = a + m;
        d0 += a * gate_w[c * 2 + 0];
        d1 += a * gate_w[c * 2 + 1];
    }
    if (tid == 0) { pool[0] = 0.0f; pool[CH + 1] = 0.0f; }
    red0[tid] = d0;
    red1[tid] = d1;
    __syncthreads();
    for (int sft = 128; sft > 0; sft >>= 1) {
        if (tid < sft) {
            red0[tid] += red0[tid + sft];
            red1[tid] += red1[tid + sft];
        }
        __syncthreads();
    }
    if (tid == 0) {
        const float l0 = red0[0] + gate_b[0];
        const float l1 = red1[0] + gate_b[1];
        const float m  = fmaxf(l0, l1);
        const float e0 = expf(l0 - m), e1 = expf(l1 - m);
        const float inv = 1.0f / (e0 + e1);
        gw0s = e0 * inv;
        gw1s = e1 * inv;
    }
    __syncthreads();

    const float c0 = ca_w[0], c1 = ca_w[1], c2 = ca_w[2];
    const float r0 = ra_w[0], r1 = ra_w[1], r2 = ra_w[2];
    const float gw0 = gw0s, gw1 = gw1s;
    for (int c = tid; c < CH; c += 256) {
        const float pm = pool[c], pc = pool[c + 1], pp = pool[c + 2];
        const float cav = c0 * pm + c1 * pc + c2 * pp;
        const float rav = r0 * pm + r1 * pc + r2 * pp;
        const float cas = 1.0f / (1.0f + expf(-cav));
        const float ras = 1.0f - 1.0f / (1.0f + expf(-rav));
        g_scale[sb * CH + c] = gw0 * cas + gw1 * ras;
    }
}

// ---------------------------------------------------------------------------
// Elementwise (in place on g_hch halves): h <- half(gelu_exact(h * scale))
// ---------------------------------------------------------------------------
__device__ __forceinline__ float gelu_exact(float v)
{
    return 0.5f * v * (1.0f + erff(v * 0.70710678118654752440f));
}

__global__ void __launch_bounds__(256)
gelu_scale_kernel()
{
    const size_t nvec = (size_t)MROWS * CH / 4;
    const size_t i = (size_t)blockIdx.x * blockDim.x + threadIdx.x;
    if (i >= nvec) return;
    const size_t e   = i * 4;
    const int    row = (int)(e / CH);
    const int    c   = (int)(e % CH);
    const int    b   = row / NTOK;
    const int    tok = row % NTOK;
    const int    s   = (tok < 4096) ? 0 : ((tok < 5120) ? 1 : 2);

    uint32_t* hp = (uint32_t*)g_hch;
    uint2 hv = *(uint2*)(hp + i * 2);
    float4 sc = *(const float4*)(g_scale + (s * 8 + b) * CH + c);

    float2 v0 = __half22float2(*(__half2*)&hv.x);
    float2 v1 = __half22float2(*(__half2*)&hv.y);
    uint2 o;
    o.x = pack_h2(gelu_exact(v0.x * sc.x), gelu_exact(v0.y * sc.y));
    o.y = pack_h2(gelu_exact(v1.x * sc.z), gelu_exact(v1.y * sc.w));
    *(uint2*)(hp + i * 2) = o;
}

// ---------------------------------------------------------------------------
// Entry point
// ---------------------------------------------------------------------------
extern "C" void kernel_launch(void* const* d_in, const int* in_sizes, int n_in,
                              void* d_out, int out_size)
{
    const float* x      = (const float*)d_in[0];
    const float* fc1_w  = (const float*)d_in[1];
    const float* fc1_b  = (const float*)d_in[2];
    const float* dw_w   = (const float*)d_in[3];
    const float* dw_b   = (const float*)d_in[4];
    const float* ca_w   = (const float*)d_in[5];
    const float* ra_w   = (const float*)d_in[6];
    const float* gate_w = (const float*)d_in[7];
    const float* gate_b = (const float*)d_in[8];
    const float* fc2_w  = (const float*)d_in[9];
    const float* fc2_b  = (const float*)d_in[10];
    float* out = (float*)d_out;

    uint32_t *xh, *w1p, *w2p;
    __half *h1h, *hch;
    cudaGetSymbolAddress((void**)&xh,  g_xh);
    cudaGetSymbolAddress((void**)&h1h, g_h1h);
    cudaGetSymbolAddress((void**)&hch, g_hch);
    cudaGetSymbolAddress((void**)&w1p, g_w1p);
    cudaGetSymbolAddress((void**)&w2p, g_w2p);

    cudaFuncSetAttribute(gemm_f16<true>,  cudaFuncAttributeMaxDynamicSharedMemorySize, GEMM_SMEM);
    cudaFuncSetAttribute(gemm_f16<false>, cudaFuncAttributeMaxDynamicSharedMemorySize, GEMM_SMEM);

    // convert inputs & weights to fp16
    convert_x_kernel<<<(MROWS * CIN / 4 + 255) / 256, 256>>>(x);
    pack_w_kernel<<<((CIN / 2) * CH + 255) / 256, 256>>>(fc1_w, w1p, CIN / 2, CH);
    pack_w_kernel<<<((CH / 2) * CIN + 255) / 256, 256>>>(fc2_w, w2p, CH / 2, CIN);

    // fc1: (43008 x 384) @ (384 x 768) -> g_h1h (half)
    gemm_f16<true><<<dim3(CH / BN, MROWS / BM), 128, GEMM_SMEM>>>(
        xh, w1p, fc1_b, h1h, CH, CIN / 2);

    // depthwise conv + pooled stats (half in/out)
    dwconv_kernel<<<dim3(CH / 32, BB, 3), 256>>>(dw_w, dw_b);

    // gate softmax + SE channel gates
    gate_scale_kernel<<<24, 256>>>(gate_w, gate_b, ca_w, ra_w);

    // scale + exact GELU, in place on g_hch
    const int nvec = MROWS * CH / 4;
    gelu_scale_kernel<<<(nvec + 255) / 256, 256>>>();

    // fc2: (43008 x 768) @ (768 x 384) + bias -> out (fp32)
    gemm_f16<false><<<dim3(CIN / BN, MROWS / BM), 128, GEMM_SMEM>>>(
        (const uint32_t*)hch, w2p, fc2_b, out, CIN, CH / 2);
}

// round 7
// speedup vs baseline: 1.3446x; 1.0071x over previous
#include <cuda_runtime.h>
#include <cuda_fp16.h>
#include <math.h>
#include <stdint.h>

// ---------------------------------------------------------------------------
// Problem constants (B=8, N=5376, Cin=384, Ch=768, H=W=32, n=256)
// ---------------------------------------------------------------------------
#define BB      8
#define NTOK    5376
#define CIN     384
#define CH      768
#define MROWS   (BB * NTOK)          // 43008

// ---------------------------------------------------------------------------
// Scratch (device globals; no runtime allocation)
// ---------------------------------------------------------------------------
__device__ uint32_t g_xh [(size_t)MROWS * CIN / 2];   // x as half pairs along K
__device__ __half   g_h1h[(size_t)MROWS * CH];        // fc1 output, half
__device__ __half   g_hch[(size_t)MROWS * CH];        // dwconv out -> gelu'd in place
__device__ uint32_t g_w1p[(CIN / 2) * CH];            // fc1_w pair-interleaved
__device__ uint32_t g_w2p[(CH / 2) * CIN];            // fc2_w pair-interleaved
__device__ float    g_avg[24 * CH];
__device__ float    g_max[24 * CH];
__device__ float    g_scale[24 * CH];

// ---------------------------------------------------------------------------
// Helpers
// ---------------------------------------------------------------------------
__device__ __forceinline__ uint32_t smem_u32(const void* p) {
    uint32_t a;
    asm("{ .reg .u64 t; cvta.to.shared.u64 t, %1; cvt.u32.u64 %0, t; }"
        : "=r"(a) : "l"(p));
    return a;
}
__device__ __forceinline__ void cp16(uint32_t d, const void* s) {
    asm volatile("cp.async.cg.shared.global [%0], [%1], 16;\n" :: "r"(d), "l"(s));
}
__device__ __forceinline__ uint32_t pack_h2(float a, float b) {
    __half2 h = __floats2half2_rn(a, b);
    return *(uint32_t*)&h;
}
__device__ __forceinline__ void mma_f16(float& d0, float& d1, float& d2, float& d3,
                                        uint32_t a0, uint32_t a1, uint32_t a2, uint32_t a3,
                                        uint32_t b0, uint32_t b1) {
    asm volatile(
        "mma.sync.aligned.m16n8k16.row.col.f32.f16.f16.f32 "
        "{%0,%1,%2,%3}, {%4,%5,%6,%7}, {%8,%9}, {%0,%1,%2,%3};\n"
        : "+f"(d0), "+f"(d1), "+f"(d2), "+f"(d3)
        : "r"(a0), "r"(a1), "r"(a2), "r"(a3), "r"(b0), "r"(b1));
}
__device__ __forceinline__ void ldsm_x4(uint32_t& r0, uint32_t& r1,
                                        uint32_t& r2, uint32_t& r3, uint32_t addr) {
    asm volatile("ldmatrix.sync.aligned.m8n8.x4.shared.b16 {%0,%1,%2,%3}, [%4];"
                 : "=r"(r0), "=r"(r1), "=r"(r2), "=r"(r3) : "r"(addr));
}

// ---------------------------------------------------------------------------
// FP16 GEMM: C[M,N] = A[M,K] @ W[K,N] + bias[N]   (fp32 accum)
// A: [M][K2] u32 half-pairs along K.  Wp: [K2][N] u32 pair-interleaved.
// 128 threads (4 warps, 2m x 2n), warp tile 64x48, BM=128 BN=96 BK2=16,
// ldmatrix.x4 A-fragments, 4-stage cp.async, 3 CTAs/SM target.
// ---------------------------------------------------------------------------
#define BM 128
#define BN 96
#define BK2 16
#define AROW 20
#define BROW 104
#define STAGES 4
#define AS_STAGE (BM * AROW)          // 2560 u32
#define BS_STAGE (BK2 * BROW)         // 1664 u32
#define GEMM_SMEM ((STAGES * (AS_STAGE + BS_STAGE)) * 4)   // 67584 bytes

template<bool HALF_OUT>
__global__ void __launch_bounds__(128, 3)
gemm_f16(const uint32_t* __restrict__ A, const uint32_t* __restrict__ Wp,
         const float* __restrict__ bias, void* __restrict__ Cout,
         int N, int K2)
{
    extern __shared__ uint32_t sm[];
    uint32_t* AsBase = sm;
    uint32_t* BsBase = sm + STAGES * AS_STAGE;

    const int tid  = threadIdx.x;
    const int brow = blockIdx.y * BM;
    const int bcol = blockIdx.x * BN;

    const int lane = tid & 31;
    const int wid  = tid >> 5;
    const int g    = lane >> 2;
    const int tig  = lane & 3;
    const int wm   = wid & 1;      // warp m (64 rows)
    const int wn   = wid >> 1;     // warp n (48 cols)

    const uint32_t asU = smem_u32(AsBase);
    const uint32_t bsU = smem_u32(BsBase);

    float acc[4][6][4];
#pragma unroll
    for (int mt = 0; mt < 4; mt++)
#pragma unroll
        for (int nt = 0; nt < 6; nt++)
#pragma unroll
            for (int v = 0; v < 4; v++) acc[mt][nt][v] = 0.0f;

    const int KT = K2 / BK2;

    auto load_stage = [&](int st, int kt) {
        const uint32_t aD = asU + (uint32_t)(st * AS_STAGE * 4);
        const uint32_t bD = bsU + (uint32_t)(st * BS_STAGE * 4);
#pragma unroll
        for (int u = 0; u < 4; u++) {
            const int li = u * 128 + tid;
            const int r = li >> 2;
            const int c = (li & 3) * 4;
            cp16(aD + (uint32_t)((r * AROW + c) * 4),
                 A + (size_t)(brow + r) * K2 + kt * BK2 + c);
        }
#pragma unroll
        for (int u = 0; u < 3; u++) {
            const int li = u * 128 + tid;       // 0..383
            const int r = li / 24;              // 0..15
            const int c = (li % 24) * 4;        // 0..92
            cp16(bD + (uint32_t)((r * BROW + c) * 4),
                 Wp + (size_t)(kt * BK2 + r) * N + bcol + c);
        }
    };

#pragma unroll
    for (int s = 0; s < STAGES - 1; s++) {
        load_stage(s, s);
        asm volatile("cp.async.commit_group;" ::: "memory");
    }

    const int lm_row  = lane & 15;
    const int lm_koff = (lane >> 4) << 2;

    for (int kt = 0; kt < KT; kt++) {
        const int cur = kt & (STAGES - 1);
        asm volatile("cp.async.wait_group 2;" ::: "memory");
        __syncthreads();

        if (kt + STAGES - 1 < KT)
            load_stage((kt + STAGES - 1) & (STAGES - 1), kt + STAGES - 1);
        asm volatile("cp.async.commit_group;" ::: "memory");

        const uint32_t  aStage = asU + (uint32_t)(cur * AS_STAGE * 4);
        const uint32_t* Bsu    = BsBase + cur * BS_STAGE;

#pragma unroll
        for (int kc = 0; kc < BK2; kc += 8) {
            uint32_t af[4][4], bf[6][2];
#pragma unroll
            for (int mt = 0; mt < 4; mt++) {
                const int r = wm * 64 + mt * 16 + lm_row;
                const uint32_t addr = aStage + (uint32_t)((r * AROW + kc + lm_koff) * 4);
                ldsm_x4(af[mt][0], af[mt][1], af[mt][2], af[mt][3], addr);
            }
#pragma unroll
            for (int nt = 0; nt < 6; nt++) {
                const int c0 = wn * 48 + nt * 8 + g;
                bf[nt][0] = Bsu[(kc + tig    ) * BROW + c0];
                bf[nt][1] = Bsu[(kc + tig + 4) * BROW + c0];
            }
#pragma unroll
            for (int mt = 0; mt < 4; mt++)
#pragma unroll
                for (int nt = 0; nt < 6; nt++)
                    mma_f16(acc[mt][nt][0], acc[mt][nt][1], acc[mt][nt][2], acc[mt][nt][3],
                            af[mt][0], af[mt][1], af[mt][2], af[mt][3],
                            bf[nt][0], bf[nt][1]);
        }
    }

    // ---- epilogue ----
#pragma unroll
    for (int nt = 0; nt < 6; nt++) {
        const int col = bcol + wn * 48 + nt * 8 + 2 * tig;
        const float b0 = bias[col];
        const float b1 = bias[col + 1];
#pragma unroll
        for (int mt = 0; mt < 4; mt++) {
            const int row0 = brow + wm * 64 + mt * 16 + g;
            if (HALF_OUT) {
                uint32_t* Ch = (uint32_t*)Cout;
                Ch[(size_t)row0 * (N / 2) + col / 2] =
                    pack_h2(acc[mt][nt][0] + b0, acc[mt][nt][1] + b1);
                Ch[(size_t)(row0 + 8) * (N / 2) + col / 2] =
                    pack_h2(acc[mt][nt][2] + b0, acc[mt][nt][3] + b1);
            } else {
                float* Cf = (float*)Cout;
                *(float2*)(Cf + (size_t)row0 * N + col) =
                    make_float2(acc[mt][nt][0] + b0, acc[mt][nt][1] + b1);
                *(float2*)(Cf + (size_t)(row0 + 8) * N + col) =
                    make_float2(acc[mt][nt][2] + b0, acc[mt][nt][3] + b1);
            }
        }
    }
}

// ---------------------------------------------------------------------------
// Convert x -> plain half (g_xh)
// ---------------------------------------------------------------------------
__global__ void __launch_bounds__(256)
convert_x_kernel(const float* __restrict__ x)
{
    const size_t i = (size_t)blockIdx.x * 256 + threadIdx.x;
    const size_t nvec = (size_t)MROWS * CIN / 4;
    if (i >= nvec) return;
    float4 v = *(const float4*)(x + i * 4);
    uint2 o;
    o.x = pack_h2(v.x, v.y);
    o.y = pack_h2(v.z, v.w);
    *(uint2*)(g_xh + i * 2) = o;
}

// ---------------------------------------------------------------------------
// Pack weights: out[k2*N + n] = half2(in[2k2][n], in[2k2+1][n])
// ---------------------------------------------------------------------------
__global__ void __launch_bounds__(256)
pack_w_kernel(const float* __restrict__ in, uint32_t* __restrict__ out,
              int K2, int N)
{
    const int idx = blockIdx.x * 256 + threadIdx.x;
    if (idx >= K2 * N) return;
    const int k2 = idx / N;
    const int n  = idx % N;
    out[idx] = pack_h2(in[(size_t)(2 * k2) * N + n],
                       in[(size_t)(2 * k2 + 1) * N + n]);
}

// ---------------------------------------------------------------------------
// Depthwise 3x3 conv, half2-vectorized (2 channels/lane), fp32 accum,
// + per-(scale,b,c) sum & max. Grid (12, 8, 3), block 256.
// ---------------------------------------------------------------------------
__global__ void __launch_bounds__(256)
dwconv_kernel(const float* __restrict__ dw_w, const float* __restrict__ dw_b)
{
    const int s  = blockIdx.z;
    const int b  = blockIdx.y;
    const int cc = blockIdx.x;          // 0..11 (64 channels each)

    const int offs[3] = {0, 4096, 5120};
    const int lws[3]  = {6, 5, 4};
    const int off = offs[s];
    const int lw  = lws[s];
    const int w   = 1 << lw;
    const int ntok = w * w;

    const int tid   = threadIdx.x;
    const int lane  = tid & 31;
    const int tslot = tid >> 5;
    const int c2    = cc * 32 + lane;   // half2 channel index (2 channels)

    float wA[9], wB[9];
#pragma unroll
    for (int i = 0; i < 9; i++) {
        wA[i] = dw_w[(2 * c2)     * 9 + i];
        wB[i] = dw_w[(2 * c2 + 1) * 9 + i];
    }
    const float bkA = dw_b[2 * c2];
    const float bkB = dw_b[2 * c2 + 1];

    const __half2* base  = (const __half2*)g_h1h + (size_t)(b * NTOK + off) * (CH / 2) + c2;
    __half2*       obase = (__half2*)g_hch       + (size_t)(b * NTOK + off) * (CH / 2) + c2;

    float sA = 0.0f, sB = 0.0f;
    float mA = -INFINITY, mB = -INFINITY;

    for (int tok = tslot; tok < ntok; tok += 8) {
        const int y = tok >> lw;
        const int x = tok & (w - 1);
        float accA = bkA, accB = bkB;
#pragma unroll
        for (int ky = 0; ky < 3; ky++) {
            const int yy = y + ky - 1;
            if ((unsigned)yy < (unsigned)w) {
                const int rb = yy << lw;
#pragma unroll
                for (int kx = 0; kx < 3; kx++) {
                    const int xx = x + kx - 1;
                    if ((unsigned)xx < (unsigned)w) {
                        float2 v = __half22float2(base[(size_t)(rb + xx) * (CH / 2)]);
                        accA += wA[ky * 3 + kx] * v.x;
                        accB += wB[ky * 3 + kx] * v.y;
                    }
                }
            }
        }
        obase[(size_t)tok * (CH / 2)] = __floats2half2_rn(accA, accB);
        sA += accA; sB += accB;
        mA = fmaxf(mA, accA); mB = fmaxf(mB, accB);
    }

    __shared__ float2 ssum[256];
    __shared__ float2 smax[256];
    ssum[tid] = make_float2(sA, sB);
    smax[tid] = make_float2(mA, mB);
    __syncthreads();
    if (tslot == 0) {
        float tsA = sA, tsB = sB, tmA = mA, tmB = mB;
#pragma unroll
        for (int j = 1; j < 8; j++) {
            float2 v = ssum[j * 32 + lane];
            float2 m = smax[j * 32 + lane];
            tsA += v.x; tsB += v.y;
            tmA = fmaxf(tmA, m.x); tmB = fmaxf(tmB, m.y);
        }
        const int sb = s * 8 + b;
        const float inv = 1.0f / (float)ntok;
        g_avg[sb * CH + 2 * c2]     = tsA * inv;
        g_avg[sb * CH + 2 * c2 + 1] = tsB * inv;
        g_max[sb * CH + 2 * c2]     = tmA;
        g_max[sb * CH + 2 * c2 + 1] = tmB;
    }
}

// ---------------------------------------------------------------------------
// Gate softmax + SE channel gates (unchanged)
// ---------------------------------------------------------------------------
__global__ void __launch_bounds__(256)
gate_scale_kernel(const float* __restrict__ gate_w, const float* __restrict__ gate_b,
                  const float* __restrict__ ca_w,   const float* __restrict__ ra_w)
{
    const int sb  = blockIdx.x;
    const int tid = threadIdx.x;

    __shared__ float pool[CH + 2];
    __shared__ float red0[256];
    __shared__ float red1[256];
    __shared__ float gw0s, gw1s;

    float d0 = 0.0f, d1 = 0.0f;
    for (int c = tid; c < CH; c += 256) {
        const float a = g_avg[sb * CH + c];
        const float m = g_max[sb * CH + c];
        pool[c + 1] = a + m;
        d0 += a * gate_w[c * 2 + 0];
        d1 += a * gate_w[c * 2 + 1];
    }
    if (tid == 0) { pool[0] = 0.0f; pool[CH + 1] = 0.0f; }
    red0[tid] = d0;
    red1[tid] = d1;
    __syncthreads();
    for (int sft = 128; sft > 0; sft >>= 1) {
        if (tid < sft) {
            red0[tid] += red0[tid + sft];
            red1[tid] += red1[tid + sft];
        }
        __syncthreads();
    }
    if (tid == 0) {
        const float l0 = red0[0] + gate_b[0];
        const float l1 = red1[0] + gate_b[1];
        const float m  = fmaxf(l0, l1);
        const float e0 = expf(l0 - m), e1 = expf(l1 - m);
        const float inv = 1.0f / (e0 + e1);
        gw0s = e0 * inv;
        gw1s = e1 * inv;
    }
    __syncthreads();

    const float c0 = ca_w[0], c1 = ca_w[1], c2 = ca_w[2];
    const float r0 = ra_w[0], r1 = ra_w[1], r2 = ra_w[2];
    const float gw0 = gw0s, gw1 = gw1s;
    for (int c = tid; c < CH; c += 256) {
        const float pm = pool[c], pc = pool[c + 1], pp = pool[c + 2];
        const float cav = c0 * pm + c1 * pc + c2 * pp;
        const float rav = r0 * pm + r1 * pc + r2 * pp;
        const float cas = 1.0f / (1.0f + expf(-cav));
        const float ras = 1.0f - 1.0f / (1.0f + expf(-rav));
        g_scale[sb * CH + c] = gw0 * cas + gw1 * ras;
    }
}

// ---------------------------------------------------------------------------
// Elementwise in place on g_hch: h <- half(gelu_exact(h * scale)), uint4/thread
// ---------------------------------------------------------------------------
__device__ __forceinline__ float gelu_exact(float v)
{
    return 0.5f * v * (1.0f + erff(v * 0.70710678118654752440f));
}

__global__ void __launch_bounds__(256)
gelu_scale_kernel()
{
    const size_t nvec = (size_t)MROWS * CH / 8;
    const size_t i = (size_t)blockIdx.x * blockDim.x + threadIdx.x;
    if (i >= nvec) return;
    const size_t e   = i * 8;
    const int    row = (int)(e / CH);
    const int    c   = (int)(e % CH);
    const int    b   = row / NTOK;
    const int    tok = row % NTOK;
    const int    s   = (tok < 4096) ? 0 : ((tok < 5120) ? 1 : 2);

    uint4 hv = *((uint4*)g_hch + i);
    const float* sp = g_scale + (s * 8 + b) * CH + c;
    float4 sc0 = *(const float4*)sp;
    float4 sc1 = *(const float4*)(sp + 4);

    float2 v0 = __half22float2(*(__half2*)&hv.x);
    float2 v1 = __half22float2(*(__half2*)&hv.y);
    float2 v2 = __half22float2(*(__half2*)&hv.z);
    float2 v3 = __half22float2(*(__half2*)&hv.w);
    uint4 o;
    o.x = pack_h2(gelu_exact(v0.x * sc0.x), gelu_exact(v0.y * sc0.y));
    o.y = pack_h2(gelu_exact(v1.x * sc0.z), gelu_exact(v1.y * sc0.w));
    o.z = pack_h2(gelu_exact(v2.x * sc1.x), gelu_exact(v2.y * sc1.y));
    o.w = pack_h2(gelu_exact(v3.x * sc1.z), gelu_exact(v3.y * sc1.w));
    *((uint4*)g_hch + i) = o;
}

// ---------------------------------------------------------------------------
// Entry point
// ---------------------------------------------------------------------------
extern "C" void kernel_launch(void* const* d_in, const int* in_sizes, int n_in,
                              void* d_out, int out_size)
{
    const float* x      = (const float*)d_in[0];
    const float* fc1_w  = (const float*)d_in[1];
    const float* fc1_b  = (const float*)d_in[2];
    const float* dw_w   = (const float*)d_in[3];
    const float* dw_b   = (const float*)d_in[4];
    const float* ca_w   = (const float*)d_in[5];
    const float* ra_w   = (const float*)d_in[6];
    const float* gate_w = (const float*)d_in[7];
    const float* gate_b = (const float*)d_in[8];
    const float* fc2_w  = (const float*)d_in[9];
    const float* fc2_b  = (const float*)d_in[10];
    float* out = (float*)d_out;

    uint32_t *xh, *w1p, *w2p;
    __half *h1h, *hch;
    cudaGetSymbolAddress((void**)&xh,  g_xh);
    cudaGetSymbolAddress((void**)&h1h, g_h1h);
    cudaGetSymbolAddress((void**)&hch, g_hch);
    cudaGetSymbolAddress((void**)&w1p, g_w1p);
    cudaGetSymbolAddress((void**)&w2p, g_w2p);

    cudaFuncSetAttribute(gemm_f16<true>,  cudaFuncAttributeMaxDynamicSharedMemorySize, GEMM_SMEM);
    cudaFuncSetAttribute(gemm_f16<false>, cudaFuncAttributeMaxDynamicSharedMemorySize, GEMM_SMEM);

    // convert inputs & weights to fp16
    convert_x_kernel<<<(MROWS * CIN / 4 + 255) / 256, 256>>>(x);
    pack_w_kernel<<<((CIN / 2) * CH + 255) / 256, 256>>>(fc1_w, w1p, CIN / 2, CH);
    pack_w_kernel<<<((CH / 2) * CIN + 255) / 256, 256>>>(fc2_w, w2p, CH / 2, CIN);

    // fc1: (43008 x 384) @ (384 x 768) -> g_h1h (half)
    gemm_f16<true><<<dim3(CH / BN, MROWS / BM), 128, GEMM_SMEM>>>(
        xh, w1p, fc1_b, h1h, CH, CIN / 2);

    // depthwise conv + pooled stats (half2-vectorized)
    dwconv_kernel<<<dim3(CH / 64, BB, 3), 256>>>(dw_w, dw_b);

    // gate softmax + SE channel gates
    gate_scale_kernel<<<24, 256>>>(gate_w, gate_b, ca_w, ra_w);

    // scale + exact GELU, in place on g_hch
    const size_t nvec = (size_t)MROWS * CH / 8;
    gelu_scale_kernel<<<(unsigned)((nvec + 255) / 256), 256>>>();

    // fc2: (43008 x 768) @ (768 x 384) + bias -> out (fp32)
    gemm_f16<false><<<dim3(CIN / BN, MROWS / BM), 128, GEMM_SMEM>>>(
        (const uint32_t*)hch, w2p, fc2_b, out, CIN, CH / 2);
}

// round 8
// speedup vs baseline: 2.3529x; 1.7499x over previous
#include <cuda_runtime.h>
#include <cuda_fp16.h>
#include <math.h>
#include <stdint.h>

// ---------------------------------------------------------------------------
// Problem constants (B=8, N=5376, Cin=384, Ch=768, H=W=32, n=256)
// ---------------------------------------------------------------------------
#define BB      8
#define NTOK    5376
#define CIN     384
#define CH      768
#define MROWS   (BB * NTOK)          // 43008
#define NCHUNK  21                   // 16 (s0) + 4 (s1) + 1 (s2), 256 tokens each

// ---------------------------------------------------------------------------
// Scratch (device globals; no runtime allocation)
// ---------------------------------------------------------------------------
__device__ uint32_t g_xh [(size_t)MROWS * CIN / 2];   // x as half pairs along K
__device__ __half   g_h1h[(size_t)MROWS * CH];        // fc1 output, half
__device__ __half   g_hch[(size_t)MROWS * CH];        // dwconv out -> gelu'd in place
__device__ uint32_t g_w1p[(CIN / 2) * CH];            // fc1_w pair-interleaved
__device__ uint32_t g_w2p[(CH / 2) * CIN];            // fc2_w pair-interleaved
__device__ float    g_psum[BB * NCHUNK * CH];         // per-chunk partial sums
__device__ float    g_pmax[BB * NCHUNK * CH];         // per-chunk partial maxes
__device__ float    g_scale[24 * CH];

// ---------------------------------------------------------------------------
// Helpers
// ---------------------------------------------------------------------------
__device__ __forceinline__ uint32_t smem_u32(const void* p) {
    uint32_t a;
    asm("{ .reg .u64 t; cvta.to.shared.u64 t, %1; cvt.u32.u64 %0, t; }"
        : "=r"(a) : "l"(p));
    return a;
}
__device__ __forceinline__ void cp16(uint32_t d, const void* s) {
    asm volatile("cp.async.cg.shared.global [%0], [%1], 16;\n" :: "r"(d), "l"(s));
}
__device__ __forceinline__ uint32_t pack_h2(float a, float b) {
    __half2 h = __floats2half2_rn(a, b);
    return *(uint32_t*)&h;
}
__device__ __forceinline__ void mma_f16(float& d0, float& d1, float& d2, float& d3,
                                        uint32_t a0, uint32_t a1, uint32_t a2, uint32_t a3,
                                        uint32_t b0, uint32_t b1) {
    asm volatile(
        "mma.sync.aligned.m16n8k16.row.col.f32.f16.f16.f32 "
        "{%0,%1,%2,%3}, {%4,%5,%6,%7}, {%8,%9}, {%0,%1,%2,%3};\n"
        : "+f"(d0), "+f"(d1), "+f"(d2), "+f"(d3)
        : "r"(a0), "r"(a1), "r"(a2), "r"(a3), "r"(b0), "r"(b1));
}
__device__ __forceinline__ void ldsm_x4(uint32_t& r0, uint32_t& r1,
                                        uint32_t& r2, uint32_t& r3, uint32_t addr) {
    asm volatile("ldmatrix.sync.aligned.m8n8.x4.shared.b16 {%0,%1,%2,%3}, [%4];"
                 : "=r"(r0), "=r"(r1), "=r"(r2), "=r"(r3) : "r"(addr));
}

// ---------------------------------------------------------------------------
// FP16 GEMM (R6 config): C[M,N] = A[M,K] @ W[K,N] + bias[N], fp32 accum.
// 128 threads (4 warps, 2x2), warp tile 64x64, BM=BN=128, BK2=16 (K=32),
// ldmatrix.x4 A-fragments, 4-stage cp.async.
// ---------------------------------------------------------------------------
#define BM 128
#define BN 128
#define BK2 16
#define AROW 20
#define BROW 136
#define STAGES 4
#define AS_STAGE (BM * AROW)
#define BS_STAGE (BK2 * BROW)
#define GEMM_SMEM ((STAGES * (AS_STAGE + BS_STAGE)) * 4)   // 75776 bytes

template<bool HALF_OUT>
__global__ void __launch_bounds__(128, 2)
gemm_f16(const uint32_t* __restrict__ A, const uint32_t* __restrict__ Wp,
         const float* __restrict__ bias, void* __restrict__ Cout,
         int N, int K2)
{
    extern __shared__ uint32_t sm[];
    uint32_t* AsBase = sm;
    uint32_t* BsBase = sm + STAGES * AS_STAGE;

    const int tid  = threadIdx.x;
    const int brow = blockIdx.y * BM;
    const int bcol = blockIdx.x * BN;

    const int lane = tid & 31;
    const int wid  = tid >> 5;
    const int g    = lane >> 2;
    const int tig  = lane & 3;
    const int wm   = wid & 1;
    const int wn   = wid >> 1;

    const uint32_t asU = smem_u32(AsBase);
    const uint32_t bsU = smem_u32(BsBase);

    float acc[4][8][4];
#pragma unroll
    for (int mt = 0; mt < 4; mt++)
#pragma unroll
        for (int nt = 0; nt < 8; nt++)
#pragma unroll
            for (int v = 0; v < 4; v++) acc[mt][nt][v] = 0.0f;

    const int KT = K2 / BK2;

    auto load_stage = [&](int st, int kt) {
        const uint32_t aD = asU + (uint32_t)(st * AS_STAGE * 4);
        const uint32_t bD = bsU + (uint32_t)(st * BS_STAGE * 4);
#pragma unroll
        for (int u = 0; u < 4; u++) {
            const int li = u * 128 + tid;
            const int r = li >> 2;
            const int c = (li & 3) * 4;
            cp16(aD + (uint32_t)((r * AROW + c) * 4),
                 A + (size_t)(brow + r) * K2 + kt * BK2 + c);
        }
#pragma unroll
        for (int u = 0; u < 4; u++) {
            const int li = u * 128 + tid;
            const int r = li >> 5;
            const int c = (li & 31) * 4;
            cp16(bD + (uint32_t)((r * BROW + c) * 4),
                 Wp + (size_t)(kt * BK2 + r) * N + bcol + c);
        }
    };

#pragma unroll
    for (int s = 0; s < STAGES - 1; s++) {
        load_stage(s, s);
        asm volatile("cp.async.commit_group;" ::: "memory");
    }

    const int lm_row  = lane & 15;
    const int lm_koff = (lane >> 4) << 2;

    for (int kt = 0; kt < KT; kt++) {
        const int cur = kt & (STAGES - 1);
        asm volatile("cp.async.wait_group 2;" ::: "memory");
        __syncthreads();

        if (kt + STAGES - 1 < KT)
            load_stage((kt + STAGES - 1) & (STAGES - 1), kt + STAGES - 1);
        asm volatile("cp.async.commit_group;" ::: "memory");

        const uint32_t  aStage = asU + (uint32_t)(cur * AS_STAGE * 4);
        const uint32_t* Bsu    = BsBase + cur * BS_STAGE;

#pragma unroll
        for (int kc = 0; kc < BK2; kc += 8) {
            uint32_t af[4][4], bf[8][2];
#pragma unroll
            for (int mt = 0; mt < 4; mt++) {
                const int r = wm * 64 + mt * 16 + lm_row;
                const uint32_t addr = aStage + (uint32_t)((r * AROW + kc + lm_koff) * 4);
                ldsm_x4(af[mt][0], af[mt][1], af[mt][2], af[mt][3], addr);
            }
#pragma unroll
            for (int nt = 0; nt < 8; nt++) {
                const int c0 = wn * 64 + nt * 8 + g;
                bf[nt][0] = Bsu[(kc + tig    ) * BROW + c0];
                bf[nt][1] = Bsu[(kc + tig + 4) * BROW + c0];
            }
#pragma unroll
            for (int mt = 0; mt < 4; mt++)
#pragma unroll
                for (int nt = 0; nt < 8; nt++)
                    mma_f16(acc[mt][nt][0], acc[mt][nt][1], acc[mt][nt][2], acc[mt][nt][3],
                            af[mt][0], af[mt][1], af[mt][2], af[mt][3],
                            bf[nt][0], bf[nt][1]);
        }
    }

    // ---- epilogue ----
#pragma unroll
    for (int nt = 0; nt < 8; nt++) {
        const int col = bcol + wn * 64 + nt * 8 + 2 * tig;
        const float b0 = bias[col];
        const float b1 = bias[col + 1];
#pragma unroll
        for (int mt = 0; mt < 4; mt++) {
            const int row0 = brow + wm * 64 + mt * 16 + g;
            if (HALF_OUT) {
                uint32_t* Ch = (uint32_t*)Cout;
                Ch[(size_t)row0 * (N / 2) + col / 2] =
                    pack_h2(acc[mt][nt][0] + b0, acc[mt][nt][1] + b1);
                Ch[(size_t)(row0 + 8) * (N / 2) + col / 2] =
                    pack_h2(acc[mt][nt][2] + b0, acc[mt][nt][3] + b1);
            } else {
                float* Cf = (float*)Cout;
                *(float2*)(Cf + (size_t)row0 * N + col) =
                    make_float2(acc[mt][nt][0] + b0, acc[mt][nt][1] + b1);
                *(float2*)(Cf + (size_t)(row0 + 8) * N + col) =
                    make_float2(acc[mt][nt][2] + b0, acc[mt][nt][3] + b1);
            }
        }
    }
}

// ---------------------------------------------------------------------------
// Fused prep: convert x -> half pairs; pack fc1_w, fc2_w pair-interleaved.
// ---------------------------------------------------------------------------
#define PREP_NX ((MROWS * CIN) / 4)          // uint2 convert units
#define PREP_NP ((CIN / 2) * CH)             // pack units per weight

__global__ void __launch_bounds__(256)
prep_kernel(const float* __restrict__ x,
            const float* __restrict__ w1, const float* __restrict__ w2)
{
    const int i = blockIdx.x * 256 + threadIdx.x;
    if (i < PREP_NX) {
        float4 v = *(const float4*)(x + (size_t)i * 4);
        uint2 o;
        o.x = pack_h2(v.x, v.y);
        o.y = pack_h2(v.z, v.w);
        *(uint2*)(g_xh + (size_t)i * 2) = o;
    } else if (i < PREP_NX + PREP_NP) {
        const int j  = i - PREP_NX;
        const int k2 = j / CH;
        const int n  = j % CH;
        g_w1p[j] = pack_h2(w1[(size_t)(2 * k2) * CH + n],
                           w1[(size_t)(2 * k2 + 1) * CH + n]);
    } else if (i < PREP_NX + 2 * PREP_NP) {
        const int j  = i - PREP_NX - PREP_NP;
        const int k2 = j / CIN;
        const int n  = j % CIN;
        g_w2p[j] = pack_h2(w2[(size_t)(2 * k2) * CIN + n],
                           w2[(size_t)(2 * k2 + 1) * CIN + n]);
    }
}

// ---------------------------------------------------------------------------
// Depthwise 3x3 conv, chunked (256 tokens/CTA), half2 x 2 channels per lane.
// Grid (12 ccblocks, 21 chunks, 8 batches), block 256 = 32 ch2 x 8 slots.
// Chunk map: [0,16) -> s0 (64x64), [16,20) -> s1 (32x32), 20 -> s2 (16x16).
// ---------------------------------------------------------------------------
__global__ void __launch_bounds__(256)
dwconv_kernel(const float* __restrict__ dw_w, const float* __restrict__ dw_b)
{
    const int cc  = blockIdx.x;
    const int chk = blockIdx.y;
    const int b   = blockIdx.z;

    int s, cis;
    if (chk < 16)      { s = 0; cis = chk; }
    else if (chk < 20) { s = 1; cis = chk - 16; }
    else               { s = 2; cis = 0; }

    const int offs[3] = {0, 4096, 5120};
    const int lws[3]  = {6, 5, 4};
    const int off  = offs[s];
    const int lw   = lws[s];
    const int w    = 1 << lw;
    const int tok0 = cis * 256;

    const int tid   = threadIdx.x;
    const int lane  = tid & 31;
    const int tslot = tid >> 5;
    const int c2    = cc * 32 + lane;

    float wA[9], wB[9];
#pragma unroll
    for (int i = 0; i < 9; i++) {
        wA[i] = dw_w[(2 * c2)     * 9 + i];
        wB[i] = dw_w[(2 * c2 + 1) * 9 + i];
    }
    const float bkA = dw_b[2 * c2];
    const float bkB = dw_b[2 * c2 + 1];

    const __half2* base  = (const __half2*)g_h1h + (size_t)(b * NTOK + off) * (CH / 2) + c2;
    __half2*       obase = (__half2*)g_hch       + (size_t)(b * NTOK + off) * (CH / 2) + c2;

    float sA = 0.0f, sB = 0.0f;
    float mA = -INFINITY, mB = -INFINITY;

#pragma unroll 4
    for (int t = tslot; t < 256; t += 8) {
        const int tok = tok0 + t;
        const int y = tok >> lw;
        const int x = tok & (w - 1);
        float accA = bkA, accB = bkB;
#pragma unroll
        for (int ky = 0; ky < 3; ky++) {
            const int yy = y + ky - 1;
            if ((unsigned)yy < (unsigned)w) {
                const int rb = yy << lw;
#pragma unroll
                for (int kx = 0; kx < 3; kx++) {
                    const int xx = x + kx - 1;
                    if ((unsigned)xx < (unsigned)w) {
                        float2 v = __half22float2(base[(size_t)(rb + xx) * (CH / 2)]);
                        accA += wA[ky * 3 + kx] * v.x;
                        accB += wB[ky * 3 + kx] * v.y;
                    }
                }
            }
        }
        obase[(size_t)tok * (CH / 2)] = __floats2half2_rn(accA, accB);
        sA += accA; sB += accB;
        mA = fmaxf(mA, accA); mB = fmaxf(mB, accB);
    }

    __shared__ float2 ssum[256];
    __shared__ float2 smax[256];
    ssum[tid] = make_float2(sA, sB);
    smax[tid] = make_float2(mA, mB);
    __syncthreads();
    if (tslot == 0) {
        float tsA = sA, tsB = sB, tmA = mA, tmB = mB;
#pragma unroll
        for (int j = 1; j < 8; j++) {
            float2 v = ssum[j * 32 + lane];
            float2 m = smax[j * 32 + lane];
            tsA += v.x; tsB += v.y;
            tmA = fmaxf(tmA, m.x); tmB = fmaxf(tmB, m.y);
        }
        const size_t pb = ((size_t)b * NCHUNK + chk) * CH + 2 * c2;
        g_psum[pb]     = tsA;
        g_psum[pb + 1] = tsB;
        g_pmax[pb]     = tmA;
        g_pmax[pb + 1] = tmB;
    }
}

// ---------------------------------------------------------------------------
// Gate softmax + SE channel gates; reduces the dwconv chunk partials.
// One block per (s,b) pair: sb = s*8 + b.
// ---------------------------------------------------------------------------
__global__ void __launch_bounds__(256)
gate_scale_kernel(const float* __restrict__ gate_w, const float* __restrict__ gate_b,
                  const float* __restrict__ ca_w,   const float* __restrict__ ra_w)
{
    const int sb  = blockIdx.x;
    const int s   = sb >> 3;
    const int b   = sb & 7;
    const int tid = threadIdx.x;

    const int cs   = (s == 0) ? 0 : (s == 1) ? 16 : 20;
    const int nch  = (s == 0) ? 16 : (s == 1) ? 4 : 1;
    const int ntok = (s == 0) ? 4096 : (s == 1) ? 1024 : 256;

    __shared__ float pool[CH + 2];
    __shared__ float avgs[CH];
    __shared__ float red0[256];
    __shared__ float red1[256];
    __shared__ float gw0s, gw1s;

    float d0 = 0.0f, d1 = 0.0f;
    for (int c = tid; c < CH; c += 256) {
        float sum = 0.0f, mx = -INFINITY;
        for (int j = 0; j < nch; j++) {
            const size_t pb = ((size_t)b * NCHUNK + cs + j) * CH + c;
            sum += g_psum[pb];
            mx = fmaxf(mx, g_pmax[pb]);
        }
        const float a = sum / (float)ntok;
        avgs[c] = a;
        pool[c + 1] = a + mx;
        d0 += a * gate_w[c * 2 + 0];
        d1 += a * gate_w[c * 2 + 1];
    }
    if (tid == 0) { pool[0] = 0.0f; pool[CH + 1] = 0.0f; }
    red0[tid] = d0;
    red1[tid] = d1;
    __syncthreads();
    for (int sft = 128; sft > 0; sft >>= 1) {
        if (tid < sft) {
            red0[tid] += red0[tid + sft];
            red1[tid] += red1[tid + sft];
        }
        __syncthreads();
    }
    if (tid == 0) {
        const float l0 = red0[0] + gate_b[0];
        const float l1 = red1[0] + gate_b[1];
        const float m  = fmaxf(l0, l1);
        const float e0 = expf(l0 - m), e1 = expf(l1 - m);
        const float inv = 1.0f / (e0 + e1);
        gw0s = e0 * inv;
        gw1s = e1 * inv;
    }
    __syncthreads();

    const float c0 = ca_w[0], c1 = ca_w[1], c2 = ca_w[2];
    const float r0 = ra_w[0], r1 = ra_w[1], r2 = ra_w[2];
    const float gw0 = gw0s, gw1 = gw1s;
    for (int c = tid; c < CH; c += 256) {
        const float pm = pool[c], pc = pool[c + 1], pp = pool[c + 2];
        const float cav = c0 * pm + c1 * pc + c2 * pp;
        const float rav = r0 * pm + r1 * pc + r2 * pp;
        const float cas = 1.0f / (1.0f + expf(-cav));
        const float ras = 1.0f - 1.0f / (1.0f + expf(-rav));
        g_scale[sb * CH + c] = gw0 * cas + gw1 * ras;
    }
}

// ---------------------------------------------------------------------------
// Elementwise in place on g_hch: h <- half(gelu_exact(h * scale)), uint4/thread
// ---------------------------------------------------------------------------
__device__ __forceinline__ float gelu_exact(float v)
{
    return 0.5f * v * (1.0f + erff(v * 0.70710678118654752440f));
}

__global__ void __launch_bounds__(256)
gelu_scale_kernel()
{
    const size_t nvec = (size_t)MROWS * CH / 8;
    const size_t i = (size_t)blockIdx.x * blockDim.x + threadIdx.x;
    if (i >= nvec) return;
    const size_t e   = i * 8;
    const int    row = (int)(e / CH);
    const int    c   = (int)(e % CH);
    const int    b   = row / NTOK;
    const int    tok = row % NTOK;
    const int    s   = (tok < 4096) ? 0 : ((tok < 5120) ? 1 : 2);

    uint4 hv = *((uint4*)g_hch + i);
    const float* sp = g_scale + (s * 8 + b) * CH + c;
    float4 sc0 = *(const float4*)sp;
    float4 sc1 = *(const float4*)(sp + 4);

    float2 v0 = __half22float2(*(__half2*)&hv.x);
    float2 v1 = __half22float2(*(__half2*)&hv.y);
    float2 v2 = __half22float2(*(__half2*)&hv.z);
    float2 v3 = __half22float2(*(__half2*)&hv.w);
    uint4 o;
    o.x = pack_h2(gelu_exact(v0.x * sc0.x), gelu_exact(v0.y * sc0.y));
    o.y = pack_h2(gelu_exact(v1.x * sc0.z), gelu_exact(v1.y * sc0.w));
    o.z = pack_h2(gelu_exact(v2.x * sc1.x), gelu_exact(v2.y * sc1.y));
    o.w = pack_h2(gelu_exact(v3.x * sc1.z), gelu_exact(v3.y * sc1.w));
    *((uint4*)g_hch + i) = o;
}

// ---------------------------------------------------------------------------
// Entry point
// ---------------------------------------------------------------------------
extern "C" void kernel_launch(void* const* d_in, const int* in_sizes, int n_in,
                              void* d_out, int out_size)
{
    const float* x      = (const float*)d_in[0];
    const float* fc1_w  = (const float*)d_in[1];
    const float* fc1_b  = (const float*)d_in[2];
    const float* dw_w   = (const float*)d_in[3];
    const float* dw_b   = (const float*)d_in[4];
    const float* ca_w   = (const float*)d_in[5];
    const float* ra_w   = (const float*)d_in[6];
    const float* gate_w = (const float*)d_in[7];
    const float* gate_b = (const float*)d_in[8];
    const float* fc2_w  = (const float*)d_in[9];
    const float* fc2_b  = (const float*)d_in[10];
    float* out = (float*)d_out;

    uint32_t *xh, *w1p, *w2p;
    __half *h1h, *hch;
    cudaGetSymbolAddress((void**)&xh,  g_xh);
    cudaGetSymbolAddress((void**)&h1h, g_h1h);
    cudaGetSymbolAddress((void**)&hch, g_hch);
    cudaGetSymbolAddress((void**)&w1p, g_w1p);
    cudaGetSymbolAddress((void**)&w2p, g_w2p);

    cudaFuncSetAttribute(gemm_f16<true>,  cudaFuncAttributeMaxDynamicSharedMemorySize, GEMM_SMEM);
    cudaFuncSetAttribute(gemm_f16<false>, cudaFuncAttributeMaxDynamicSharedMemorySize, GEMM_SMEM);

    // fused prep: convert x + pack both weights
    const int prep_total = PREP_NX + 2 * PREP_NP;
    prep_kernel<<<(prep_total + 255) / 256, 256>>>(x, fc1_w, fc2_w);

    // fc1: (43008 x 384) @ (384 x 768) -> g_h1h (half)
    gemm_f16<true><<<dim3(CH / BN, MROWS / BM), 128, GEMM_SMEM>>>(
        xh, w1p, fc1_b, h1h, CH, CIN / 2);

    // depthwise conv + chunked pooled stats (2016 balanced CTAs)
    dwconv_kernel<<<dim3(CH / 64, NCHUNK, BB), 256>>>(dw_w, dw_b);

    // gate softmax + SE channel gates (reduces chunk partials)
    gate_scale_kernel<<<24, 256>>>(gate_w, gate_b, ca_w, ra_w);

    // scale + exact GELU, in place on g_hch
    const size_t nvec = (size_t)MROWS * CH / 8;
    gelu_scale_kernel<<<(unsigned)((nvec + 255) / 256), 256>>>();

    // fc2: (43008 x 768) @ (768 x 384) + bias -> out (fp32)
    gemm_f16<false><<<dim3(CIN / BN, MROWS / BM), 128, GEMM_SMEM>>>(
        (const uint32_t*)hch, w2p, fc2_b, out, CIN, CH / 2);
}